// round 15
// baseline (speedup 1.0000x reference)
#include <cuda_runtime.h>
#include <math.h>

// Problem constants
#define VOCAB 50000
#define EMB   256
#define HID   512
#define BATCH 128
#define SEQ   512
#define NOUT  10

// ---------------------------------------------------------------------------
// Device scratch
// ---------------------------------------------------------------------------
__device__ float g_H[2][BATCH * HID];   // ping-pong h, layout [b][k]

struct Resolved {
    const void*  inputs;
    const float* weights;
    const float* W;
    const float* U;
    const float* b_h;
    const float* V;
    const float* b_q;
    int          is64;
};
__device__ Resolved g_R;

struct RawIn {
    const void* p[7];
    long long   sz[7];
    int         n;
};

// ---------------------------------------------------------------------------
// Resolver (proven pointer-correct): size-rank + content disambiguation.
// ---------------------------------------------------------------------------
__global__ void resolve_kernel(RawIn in)
{
    if (in.n < 7) {
        g_R.inputs  = in.p[0];
        g_R.weights = (const float*)in.p[1];
        g_R.W       = (const float*)in.p[2];
        g_R.U       = (const float*)in.p[3];
        g_R.b_h     = (const float*)in.p[4];
        g_R.V       = (const float*)in.p[5];
        g_R.b_q     = (const float*)in.p[6 < in.n ? 6 : in.n - 1];
    } else {
        int idx[7];
        for (int i = 0; i < 7; ++i) idx[i] = i;
        for (int a = 0; a < 7; ++a)
            for (int b = 0; b < 6 - a; ++b)
                if (in.sz[idx[b]] > in.sz[idx[b + 1]]) {
                    int tmp = idx[b]; idx[b] = idx[b + 1]; idx[b + 1] = tmp;
                }
        auto looks_tokens = [&](const void* ptr) -> bool {
            const int* w = (const int*)ptr;
            for (int i = 0; i < 64; ++i) {
                int v = w[i];
                if (v < 0 || v >= VOCAB) return false;
            }
            return true;
        };
        bool t3 = looks_tokens(in.p[idx[3]]);
        bool t4 = looks_tokens(in.p[idx[4]]);
        int i_in = idx[3], i_W = idx[4];
        if (t4 && !t3) { i_in = idx[4]; i_W = idx[3]; }
        g_R.b_q     = (const float*)in.p[idx[0]];
        g_R.b_h     = (const float*)in.p[idx[1]];
        g_R.V       = (const float*)in.p[idx[2]];
        g_R.inputs  = in.p[i_in];
        g_R.W       = (const float*)in.p[i_W];
        g_R.U       = (const float*)in.p[idx[5]];
        g_R.weights = (const float*)in.p[idx[6]];
    }
    const int* tw = (const int*)g_R.inputs;
    int ored = 0;
    for (int i = 1; i < 64; i += 2) ored |= tw[i];
    g_R.is64 = (ored == 0);
}

// ---------------------------------------------------------------------------
// Rational fast-tanh, MLIR math::PolynomialApproximation variant:
//   clamp to +-7.99881172180175781  <-- the ONE change vs R14 (was 7.9053111)
//   |x| < 0.0004 -> x, alpha/beta rational via fused FMA, IEEE division.
// GPU FFMA == CPU NEON FMLA (IEEE-754 fused, RN) -> bit-identical chains.
// ---------------------------------------------------------------------------
__device__ __forceinline__ float xla_tanh(float x)
{
    const float kClamp = 7.99881172180175781f;
    float xc = fminf(fmaxf(x, -kClamp), kClamp);
    float x2 = xc * xc;
    float p = fmaf(x2, -2.76076847742355e-16f, 2.00018790482477e-13f);
    p = fmaf(x2, p, -8.60467152213735e-11f);
    p = fmaf(x2, p,  5.12229709037114e-08f);
    p = fmaf(x2, p,  1.48572235717979e-05f);
    p = fmaf(x2, p,  6.37261928875436e-04f);
    p = fmaf(x2, p,  4.89352455891786e-03f);
    p = xc * p;
    float q = fmaf(x2, 1.19825839466702e-06f, 1.18534705686654e-04f);
    q = fmaf(x2, q, 2.26843463243900e-03f);
    q = fmaf(x2, q, 4.89352518554385e-03f);
    float r = __fdiv_rn(p, q);
    return (fabsf(x) < 0.0004f) ? x : r;
}

// ---------------------------------------------------------------------------
// One recurrence step — byte-identical to R14 except the clamp constant:
//   s1[b][j] = ascending-e FMA chain from 0 of x[b][e]*W[e][j]
//   s2[b][j] = ascending-k FMA chain from 0 of h[b][k]*U[k][j]
//   h_new[b][j] = xla_tanh( (s1 + s2) + b_h[j] )
// Grid: 128 CTAs = 64 b-pairs x 2 j-halves; 256 threads = one j per thread,
// two chains (two b rows) per thread. W/U loads j-coalesced, L2-resident.
// ---------------------------------------------------------------------------
__global__ void __launch_bounds__(256)
rnn_step_exact(int t)
{
    __shared__ float xs[2][EMB];
    __shared__ float hs[2][HID];
    __shared__ int   tok[2];

    const int tid = threadIdx.x;
    const int bp  = blockIdx.x >> 1;          // batch pair 0..63
    const int jh  = blockIdx.x & 1;           // j half 0..1
    const int j   = jh * 256 + tid;

    if (tid < 2) {
        int b = 2 * bp + tid;
        long long p = (long long)b * SEQ + t;   // inputs (BATCH, SEQ)
        int v = g_R.is64 ? (int)((const long long*)g_R.inputs)[p]
                         : ((const int*)g_R.inputs)[p];
        tok[tid] = min(max(v, 0), VOCAB - 1);
    }
    __syncthreads();

    const float* wts = g_R.weights;
    for (int i = tid; i < 2 * EMB; i += 256) {
        int bb = i >> 8, e = i & 255;
        xs[bb][e] = wts[(size_t)tok[bb] * EMB + e];
    }
    for (int i = tid; i < 2 * HID; i += 256) {
        int bb = i >> 9, k = i & 511;
        hs[bb][k] = (t > 0) ? g_H[t & 1][(2 * bp + bb) * HID + k] : 0.f;
    }
    __syncthreads();

    const float* W = g_R.W;
    const float* U = g_R.U;

    float s1a = 0.f, s1b = 0.f;
#pragma unroll 8
    for (int e = 0; e < EMB; ++e) {
        float w = W[(size_t)e * HID + j];
        s1a = fmaf(xs[0][e], w, s1a);
        s1b = fmaf(xs[1][e], w, s1b);
    }
    float s2a = 0.f, s2b = 0.f;
#pragma unroll 8
    for (int k = 0; k < HID; ++k) {
        float u = U[(size_t)k * HID + j];
        s2a = fmaf(hs[0][k], u, s2a);
        s2b = fmaf(hs[1][k], u, s2b);
    }

    float bh = g_R.b_h[j];
    float pa = (s1a + s2a) + bh;   // left-assoc: (x@W + h@U) + b_h
    float pb = (s1b + s2b) + bh;

    float* Hd = g_H[(t + 1) & 1];
    Hd[(2 * bp + 0) * HID + j] = xla_tanh(pa);
    Hd[(2 * bp + 1) * HID + j] = xla_tanh(pb);
}

// ---------------------------------------------------------------------------
// Head: logits = h_T @ V + b_q, softmax. Post-chaos, ulp differences harmless.
// h_T in g_H[0] (t=511 writes parity 0), layout [b][k]. One warp per row.
// ---------------------------------------------------------------------------
__global__ void head_kernel(float* __restrict__ out)
{
    const float* V   = g_R.V;
    const float* b_q = g_R.b_q;

    const int b    = blockIdx.x;
    const int lane = threadIdx.x;
    const float* h = &g_H[0][b * HID];

    float acc[NOUT];
#pragma unroll
    for (int n = 0; n < NOUT; ++n) acc[n] = 0.f;

    for (int k = lane; k < HID; k += 32) {
        float hv = h[k];
        const float* vr = &V[k * NOUT];
#pragma unroll
        for (int n = 0; n < NOUT; ++n) acc[n] = fmaf(hv, vr[n], acc[n]);
    }
#pragma unroll
    for (int off = 16; off > 0; off >>= 1) {
#pragma unroll
        for (int n = 0; n < NOUT; ++n)
            acc[n] += __shfl_down_sync(0xffffffffu, acc[n], off);
    }
    if (lane == 0) {
        float logits[NOUT], mx = -1e30f;
#pragma unroll
        for (int n = 0; n < NOUT; ++n) { logits[n] = acc[n] + b_q[n]; mx = fmaxf(mx, logits[n]); }
        float se = 0.f;
#pragma unroll
        for (int n = 0; n < NOUT; ++n) { logits[n] = expf(logits[n] - mx); se += logits[n]; }
        float inv = __fdiv_rn(1.0f, se);
#pragma unroll
        for (int n = 0; n < NOUT; ++n) out[b * NOUT + n] = logits[n] * inv;
    }
}

// ---------------------------------------------------------------------------
// Launch: resolver, 512 stream-ordered exact steps, head.
// ---------------------------------------------------------------------------
extern "C" void kernel_launch(void* const* d_in, const int* in_sizes, int n_in,
                              void* d_out, int out_size)
{
    RawIn r;
    r.n = (n_in < 7) ? n_in : 7;
    for (int i = 0; i < 7; ++i) {
        int ii = (i < n_in) ? i : (n_in - 1);
        r.p[i]  = d_in[ii];
        r.sz[i] = (long long)in_sizes[ii];
    }

    resolve_kernel<<<1, 1>>>(r);

    for (int t = 0; t < SEQ; ++t)
        rnn_step_exact<<<BATCH, 256>>>(t);

    head_kernel<<<BATCH, 32>>>((float*)d_out);
}

// round 16
// speedup vs baseline: 2.8466x; 2.8466x over previous
#include <cuda_runtime.h>
#include <math.h>

// Problem constants
#define VOCAB 50000
#define EMB   256
#define HID   512
#define BATCH 128
#define SEQ   512
#define NOUT  10

// ---------------------------------------------------------------------------
// Device scratch
// ---------------------------------------------------------------------------
__device__ float g_WE[(size_t)VOCAB * HID];   // weights @ W (NO b_h), 102.4 MB
__device__ float g_H[2][BATCH * HID];         // ping-pong h, layout [b][k]

struct Resolved {
    const void*  inputs;
    const float* weights;
    const float* W;
    const float* U;
    const float* b_h;
    const float* V;
    const float* b_q;
    int          is64;
};
__device__ Resolved g_R;

struct RawIn {
    const void* p[7];
    long long   sz[7];
    int         n;
};

// ---------------------------------------------------------------------------
// Resolver (proven pointer-correct): size-rank + content disambiguation.
// ---------------------------------------------------------------------------
__global__ void resolve_kernel(RawIn in)
{
    if (in.n < 7) {
        g_R.inputs  = in.p[0];
        g_R.weights = (const float*)in.p[1];
        g_R.W       = (const float*)in.p[2];
        g_R.U       = (const float*)in.p[3];
        g_R.b_h     = (const float*)in.p[4];
        g_R.V       = (const float*)in.p[5];
        g_R.b_q     = (const float*)in.p[6 < in.n ? 6 : in.n - 1];
    } else {
        int idx[7];
        for (int i = 0; i < 7; ++i) idx[i] = i;
        for (int a = 0; a < 7; ++a)
            for (int b = 0; b < 6 - a; ++b)
                if (in.sz[idx[b]] > in.sz[idx[b + 1]]) {
                    int tmp = idx[b]; idx[b] = idx[b + 1]; idx[b + 1] = tmp;
                }
        auto looks_tokens = [&](const void* ptr) -> bool {
            const int* w = (const int*)ptr;
            for (int i = 0; i < 64; ++i) {
                int v = w[i];
                if (v < 0 || v >= VOCAB) return false;
            }
            return true;
        };
        bool t3 = looks_tokens(in.p[idx[3]]);
        bool t4 = looks_tokens(in.p[idx[4]]);
        int i_in = idx[3], i_W = idx[4];
        if (t4 && !t3) { i_in = idx[4]; i_W = idx[3]; }
        g_R.b_q     = (const float*)in.p[idx[0]];
        g_R.b_h     = (const float*)in.p[idx[1]];
        g_R.V       = (const float*)in.p[idx[2]];
        g_R.inputs  = in.p[i_in];
        g_R.W       = (const float*)in.p[i_W];
        g_R.U       = (const float*)in.p[idx[5]];
        g_R.weights = (const float*)in.p[idx[6]];
    }
    const int* tw = (const int*)g_R.inputs;
    int ored = 0;
    for (int i = 1; i < 64; i += 2) ored |= tw[i];
    g_R.is64 = (ored == 0);
}

// ---------------------------------------------------------------------------
// Phase 1: WE[v][j] = ascending-e FMA chain of weights[v][e]*W[e][j], acc
// from 0 — BIT-IDENTICAL to the reference's per-step x@W dot (acc carried
// sequentially through 4 ascending k-chunks). b_h intentionally NOT added.
// 64x64 tile, static smem ~33 KB. 256 thr = 64 r x 4 jq, 1 row x 16 cols each.
// ---------------------------------------------------------------------------
__global__ void __launch_bounds__(256)
we_gemm_kernel()
{
    __shared__ float As[64][65];
    __shared__ float Ws[64][64];

    const float* weights = g_R.weights;
    const float* W       = g_R.W;

    const int tid = threadIdx.x;
    const int r0  = blockIdx.x * 64;
    const int j0  = blockIdx.y * 64;

    const int r  = tid & 63;
    const int jq = tid >> 6;

    float acc[16];
#pragma unroll
    for (int i = 0; i < 16; ++i) acc[i] = 0.f;

    const float4* w4 = (const float4*)weights;
    const float4* W4 = (const float4*)W;

    for (int kc = 0; kc < 4; ++kc) {
        const int kbase = kc * 64;
        __syncthreads();
        for (int idx = tid; idx < 64 * 16; idx += 256) {
            int rr = idx >> 4;
            int kq = idx & 15;
            if (r0 + rr < VOCAB) {
                float4 v = w4[(size_t)(r0 + rr) * 64 + (kbase >> 2) + kq];
                As[rr][kq * 4 + 0] = v.x; As[rr][kq * 4 + 1] = v.y;
                As[rr][kq * 4 + 2] = v.z; As[rr][kq * 4 + 3] = v.w;
            }
        }
        for (int idx = tid; idx < 64 * 16; idx += 256) {
            int kk = idx >> 4;
            int jc = idx & 15;
            float4 v = W4[(size_t)(kbase + kk) * 128 + (j0 >> 2) + jc];
            Ws[kk][jc * 4 + 0] = v.x; Ws[kk][jc * 4 + 1] = v.y;
            Ws[kk][jc * 4 + 2] = v.z; Ws[kk][jc * 4 + 3] = v.w;
        }
        __syncthreads();

#pragma unroll 4
        for (int k = 0; k < 64; ++k) {
            float a = As[r][k];
            const float4* wr = (const float4*)&Ws[k][jq << 4];
            float4 w0 = wr[0], w1 = wr[1], w2 = wr[2], w3 = wr[3];
            acc[0]  = fmaf(a, w0.x, acc[0]);  acc[1]  = fmaf(a, w0.y, acc[1]);
            acc[2]  = fmaf(a, w0.z, acc[2]);  acc[3]  = fmaf(a, w0.w, acc[3]);
            acc[4]  = fmaf(a, w1.x, acc[4]);  acc[5]  = fmaf(a, w1.y, acc[5]);
            acc[6]  = fmaf(a, w1.z, acc[6]);  acc[7]  = fmaf(a, w1.w, acc[7]);
            acc[8]  = fmaf(a, w2.x, acc[8]);  acc[9]  = fmaf(a, w2.y, acc[9]);
            acc[10] = fmaf(a, w2.z, acc[10]); acc[11] = fmaf(a, w2.w, acc[11]);
            acc[12] = fmaf(a, w3.x, acc[12]); acc[13] = fmaf(a, w3.y, acc[13]);
            acc[14] = fmaf(a, w3.z, acc[14]); acc[15] = fmaf(a, w3.w, acc[15]);
        }
    }

    int rr = r0 + r;
    if (rr < VOCAB) {
        float* dst = &g_WE[(size_t)rr * HID + j0 + (jq << 4)];
#pragma unroll
        for (int i = 0; i < 16; ++i) dst[i] = acc[i];
    }
}

// ---------------------------------------------------------------------------
// Rational fast-tanh, MLIR math::PolynomialApproximation (PROVEN bit-exact):
// clamp +-7.99881172180175781, |x|<0.0004 -> x, FMA rational, IEEE division.
// ---------------------------------------------------------------------------
__device__ __forceinline__ float xla_tanh(float x)
{
    const float kClamp = 7.99881172180175781f;
    float xc = fminf(fmaxf(x, -kClamp), kClamp);
    float x2 = xc * xc;
    float p = fmaf(x2, -2.76076847742355e-16f, 2.00018790482477e-13f);
    p = fmaf(x2, p, -8.60467152213735e-11f);
    p = fmaf(x2, p,  5.12229709037114e-08f);
    p = fmaf(x2, p,  1.48572235717979e-05f);
    p = fmaf(x2, p,  6.37261928875436e-04f);
    p = fmaf(x2, p,  4.89352455891786e-03f);
    p = xc * p;
    float q = fmaf(x2, 1.19825839466702e-06f, 1.18534705686654e-04f);
    q = fmaf(x2, q, 2.26843463243900e-03f);
    q = fmaf(x2, q, 4.89352518554385e-03f);
    float r = __fdiv_rn(p, q);
    return (fabsf(x) < 0.0004f) ? x : r;
}

// ---------------------------------------------------------------------------
// One recurrence step, fast path (bit-exact chains preserved):
//   h_new[b][j] = xla_tanh( (WE[tok[b]][j] + s2[b][j]) + b_h[j] )
//   s2 = ascending-k FMA chain from 0 of h[b][k]*U[k][j]  (UNCHANGED ORDER)
// Grid: 128 CTAs = 4 j-blocks x 32 b-groups; 128 thr = 1 j each, 4 b-chains.
//   - h staged transposed in smem: hsT[k] = (h[b0..b3][k]) -> 1 LDS.128/k
//   - U streamed with a 32-deep rotating register prefetch (32 outstanding
//     LDGs/warp covers L2 latency; chains only serialize through acc)
//   - U traffic 32 MB/step (BB=4 reuse), ~5.1K cyc L2-bound
// ---------------------------------------------------------------------------
__global__ void __launch_bounds__(128)
rnn_step_fast(int t)
{
    __shared__ float4 hsT[HID];   // 8 KB
    __shared__ int    tok[4];

    const int tid = threadIdx.x;
    const int jb  = blockIdx.x & 3;    // j-block 0..3
    const int bg  = blockIdx.x >> 2;   // b-group 0..31
    const int b0  = bg * 4;
    const int j   = jb * 128 + tid;

    if (tid < 4) {
        long long p = (long long)(b0 + tid) * SEQ + t;
        int v = g_R.is64 ? (int)((const long long*)g_R.inputs)[p]
                         : ((const int*)g_R.inputs)[p];
        tok[tid] = min(max(v, 0), VOCAB - 1);
    }
    if (t > 0) {
        const float* Hs = &g_H[t & 1][0];
#pragma unroll
        for (int q = 0; q < 4; ++q) {
            int k = tid * 4 + q;
            hsT[k] = make_float4(Hs[(b0 + 0) * HID + k], Hs[(b0 + 1) * HID + k],
                                 Hs[(b0 + 2) * HID + k], Hs[(b0 + 3) * HID + k]);
        }
    }
    __syncthreads();

    // input-projection gathers + bias (issued early, consumed after the loop)
    const float* WE = g_WE;
    float s10 = WE[(size_t)tok[0] * HID + j];
    float s11 = WE[(size_t)tok[1] * HID + j];
    float s12 = WE[(size_t)tok[2] * HID + j];
    float s13 = WE[(size_t)tok[3] * HID + j];
    float bh  = g_R.b_h[j];

    float a0 = 0.f, a1 = 0.f, a2 = 0.f, a3 = 0.f;
    if (t > 0) {
        const float* Uj = g_R.U + j;
        float ub[32];
#pragma unroll
        for (int s = 0; s < 32; ++s) ub[s] = Uj[(size_t)s * HID];

#pragma unroll 32
        for (int k = 0; k < HID; ++k) {
            float u = ub[k & 31];
            ub[k & 31] = Uj[(size_t)((k + 32) & (HID - 1)) * HID];  // prefetch
            float4 hv = hsT[k];
            a0 = fmaf(hv.x, u, a0);
            a1 = fmaf(hv.y, u, a1);
            a2 = fmaf(hv.z, u, a2);
            a3 = fmaf(hv.w, u, a3);
        }
    }

    float* Hd = g_H[(t + 1) & 1];
    Hd[(b0 + 0) * HID + j] = xla_tanh((s10 + a0) + bh);
    Hd[(b0 + 1) * HID + j] = xla_tanh((s11 + a1) + bh);
    Hd[(b0 + 2) * HID + j] = xla_tanh((s12 + a2) + bh);
    Hd[(b0 + 3) * HID + j] = xla_tanh((s13 + a3) + bh);
}

// ---------------------------------------------------------------------------
// Head: logits = h_T @ V + b_q, softmax. Post-chaos, ulp differences harmless.
// h_T in g_H[0] (t=511 writes parity 0), layout [b][k]. One warp per row.
// ---------------------------------------------------------------------------
__global__ void head_kernel(float* __restrict__ out)
{
    const float* V   = g_R.V;
    const float* b_q = g_R.b_q;

    const int b    = blockIdx.x;
    const int lane = threadIdx.x;
    const float* h = &g_H[0][b * HID];

    float acc[NOUT];
#pragma unroll
    for (int n = 0; n < NOUT; ++n) acc[n] = 0.f;

    for (int k = lane; k < HID; k += 32) {
        float hv = h[k];
        const float* vr = &V[k * NOUT];
#pragma unroll
        for (int n = 0; n < NOUT; ++n) acc[n] = fmaf(hv, vr[n], acc[n]);
    }
#pragma unroll
    for (int off = 16; off > 0; off >>= 1) {
#pragma unroll
        for (int n = 0; n < NOUT; ++n)
            acc[n] += __shfl_down_sync(0xffffffffu, acc[n], off);
    }
    if (lane == 0) {
        float logits[NOUT], mx = -1e30f;
#pragma unroll
        for (int n = 0; n < NOUT; ++n) { logits[n] = acc[n] + b_q[n]; mx = fmaxf(mx, logits[n]); }
        float se = 0.f;
#pragma unroll
        for (int n = 0; n < NOUT; ++n) { logits[n] = expf(logits[n] - mx); se += logits[n]; }
        float inv = __fdiv_rn(1.0f, se);
#pragma unroll
        for (int n = 0; n < NOUT; ++n) out[b * NOUT + n] = logits[n] * inv;
    }
}

// ---------------------------------------------------------------------------
// Launch: resolver, WE hoist GEMM, 512 stream-ordered fast steps, head.
// ---------------------------------------------------------------------------
extern "C" void kernel_launch(void* const* d_in, const int* in_sizes, int n_in,
                              void* d_out, int out_size)
{
    RawIn r;
    r.n = (n_in < 7) ? n_in : 7;
    for (int i = 0; i < 7; ++i) {
        int ii = (i < n_in) ? i : (n_in - 1);
        r.p[i]  = d_in[ii];
        r.sz[i] = (long long)in_sizes[ii];
    }

    resolve_kernel<<<1, 1>>>(r);

    dim3 grid1((VOCAB + 63) / 64, HID / 64);   // 782 x 8
    we_gemm_kernel<<<grid1, 256>>>();

    for (int t = 0; t < SEQ; ++t)
        rnn_step_fast<<<BATCH, 128>>>(t);

    head_kernel<<<BATCH, 32>>>((float*)d_out);
}

// round 17
// speedup vs baseline: 4.5026x; 1.5818x over previous
#include <cuda_runtime.h>
#include <math.h>

// Problem constants
#define VOCAB 50000
#define EMB   256
#define HID   512
#define BATCH 128
#define SEQ   512
#define NOUT  10

// Persistent tiling: 128 CTAs = 32 j-slices (16 j) x 4 b-blocks (32 b)
#define JW    16
#define BBK   32
#define NCTA  128
#define HS_STRIDE 516   // padded h row (conflict-free LDS.128 pairs)

// ---------------------------------------------------------------------------
// Device scratch
// ---------------------------------------------------------------------------
__device__ float g_WE[(size_t)VOCAB * HID];   // weights @ W (NO b_h), 102.4 MB
__device__ float g_H[2][BATCH * HID];         // ping-pong h, layout [b][k]
__device__ int   g_bar;                       // persistent-kernel step counter

struct Resolved {
    const void*  inputs;
    const float* weights;
    const float* W;
    const float* U;
    const float* b_h;
    const float* V;
    const float* b_q;
    int          is64;
};
__device__ Resolved g_R;

struct RawIn {
    const void* p[7];
    long long   sz[7];
    int         n;
};

// ---------------------------------------------------------------------------
// Resolver (proven pointer-correct): size-rank + content disambiguation.
// ---------------------------------------------------------------------------
__global__ void resolve_kernel(RawIn in)
{
    g_bar = 0;   // reset persistent barrier every launch/replay
    if (in.n < 7) {
        g_R.inputs  = in.p[0];
        g_R.weights = (const float*)in.p[1];
        g_R.W       = (const float*)in.p[2];
        g_R.U       = (const float*)in.p[3];
        g_R.b_h     = (const float*)in.p[4];
        g_R.V       = (const float*)in.p[5];
        g_R.b_q     = (const float*)in.p[6 < in.n ? 6 : in.n - 1];
    } else {
        int idx[7];
        for (int i = 0; i < 7; ++i) idx[i] = i;
        for (int a = 0; a < 7; ++a)
            for (int b = 0; b < 6 - a; ++b)
                if (in.sz[idx[b]] > in.sz[idx[b + 1]]) {
                    int tmp = idx[b]; idx[b] = idx[b + 1]; idx[b + 1] = tmp;
                }
        auto looks_tokens = [&](const void* ptr) -> bool {
            const int* w = (const int*)ptr;
            for (int i = 0; i < 64; ++i) {
                int v = w[i];
                if (v < 0 || v >= VOCAB) return false;
            }
            return true;
        };
        bool t3 = looks_tokens(in.p[idx[3]]);
        bool t4 = looks_tokens(in.p[idx[4]]);
        int i_in = idx[3], i_W = idx[4];
        if (t4 && !t3) { i_in = idx[4]; i_W = idx[3]; }
        g_R.b_q     = (const float*)in.p[idx[0]];
        g_R.b_h     = (const float*)in.p[idx[1]];
        g_R.V       = (const float*)in.p[idx[2]];
        g_R.inputs  = in.p[i_in];
        g_R.W       = (const float*)in.p[i_W];
        g_R.U       = (const float*)in.p[idx[5]];
        g_R.weights = (const float*)in.p[idx[6]];
    }
    const int* tw = (const int*)g_R.inputs;
    int ored = 0;
    for (int i = 1; i < 64; i += 2) ored |= tw[i];
    g_R.is64 = (ored == 0);
}

// ---------------------------------------------------------------------------
// Phase 1: WE[v][j] = ascending-e FMA chain of weights[v][e]*W[e][j] from 0
// (bit-identical to the reference x@W dot; b_h NOT folded in).
// ---------------------------------------------------------------------------
__global__ void __launch_bounds__(256)
we_gemm_kernel()
{
    __shared__ float As[64][65];
    __shared__ float Ws[64][64];

    const float* weights = g_R.weights;
    const float* W       = g_R.W;

    const int tid = threadIdx.x;
    const int r0  = blockIdx.x * 64;
    const int j0  = blockIdx.y * 64;

    const int r  = tid & 63;
    const int jq = tid >> 6;

    float acc[16];
#pragma unroll
    for (int i = 0; i < 16; ++i) acc[i] = 0.f;

    const float4* w4 = (const float4*)weights;
    const float4* W4 = (const float4*)W;

    for (int kc = 0; kc < 4; ++kc) {
        const int kbase = kc * 64;
        __syncthreads();
        for (int idx = tid; idx < 64 * 16; idx += 256) {
            int rr = idx >> 4;
            int kq = idx & 15;
            if (r0 + rr < VOCAB) {
                float4 v = w4[(size_t)(r0 + rr) * 64 + (kbase >> 2) + kq];
                As[rr][kq * 4 + 0] = v.x; As[rr][kq * 4 + 1] = v.y;
                As[rr][kq * 4 + 2] = v.z; As[rr][kq * 4 + 3] = v.w;
            }
        }
        for (int idx = tid; idx < 64 * 16; idx += 256) {
            int kk = idx >> 4;
            int jc = idx & 15;
            float4 v = W4[(size_t)(kbase + kk) * 128 + (j0 >> 2) + jc];
            Ws[kk][jc * 4 + 0] = v.x; Ws[kk][jc * 4 + 1] = v.y;
            Ws[kk][jc * 4 + 2] = v.z; Ws[kk][jc * 4 + 3] = v.w;
        }
        __syncthreads();

#pragma unroll 4
        for (int k = 0; k < 64; ++k) {
            float a = As[r][k];
            const float4* wr = (const float4*)&Ws[k][jq << 4];
            float4 w0 = wr[0], w1 = wr[1], w2 = wr[2], w3 = wr[3];
            acc[0]  = fmaf(a, w0.x, acc[0]);  acc[1]  = fmaf(a, w0.y, acc[1]);
            acc[2]  = fmaf(a, w0.z, acc[2]);  acc[3]  = fmaf(a, w0.w, acc[3]);
            acc[4]  = fmaf(a, w1.x, acc[4]);  acc[5]  = fmaf(a, w1.y, acc[5]);
            acc[6]  = fmaf(a, w1.z, acc[6]);  acc[7]  = fmaf(a, w1.w, acc[7]);
            acc[8]  = fmaf(a, w2.x, acc[8]);  acc[9]  = fmaf(a, w2.y, acc[9]);
            acc[10] = fmaf(a, w2.z, acc[10]); acc[11] = fmaf(a, w2.w, acc[11]);
            acc[12] = fmaf(a, w3.x, acc[12]); acc[13] = fmaf(a, w3.y, acc[13]);
            acc[14] = fmaf(a, w3.z, acc[14]); acc[15] = fmaf(a, w3.w, acc[15]);
        }
    }

    int rr = r0 + r;
    if (rr < VOCAB) {
        float* dst = &g_WE[(size_t)rr * HID + j0 + (jq << 4)];
#pragma unroll
        for (int i = 0; i < 16; ++i) dst[i] = acc[i];
    }
}

// ---------------------------------------------------------------------------
// Rational fast-tanh, MLIR math::PolynomialApproximation (PROVEN bit-exact).
// ---------------------------------------------------------------------------
__device__ __forceinline__ float xla_tanh(float x)
{
    const float kClamp = 7.99881172180175781f;
    float xc = fminf(fmaxf(x, -kClamp), kClamp);
    float x2 = xc * xc;
    float p = fmaf(x2, -2.76076847742355e-16f, 2.00018790482477e-13f);
    p = fmaf(x2, p, -8.60467152213735e-11f);
    p = fmaf(x2, p,  5.12229709037114e-08f);
    p = fmaf(x2, p,  1.48572235717979e-05f);
    p = fmaf(x2, p,  6.37261928875436e-04f);
    p = fmaf(x2, p,  4.89352455891786e-03f);
    p = xc * p;
    float q = fmaf(x2, 1.19825839466702e-06f, 1.18534705686654e-04f);
    q = fmaf(x2, q, 2.26843463243900e-03f);
    q = fmaf(x2, q, 4.89352518554385e-03f);
    float r = __fdiv_rn(p, q);
    return (fabsf(x) < 0.0004f) ? x : r;
}

// ---------------------------------------------------------------------------
// PERSISTENT recurrence: 128 CTAs x 256 thr, all 512 steps in one launch.
// CTA (jsl, bb): j-slice 16, b-block 32. U slice resident in smem the whole
// time (k-blocked [kq][jl][4] for aligned LDS.128). Per step: stage h-block
// (contiguous 64 KB) to smem, 2 bit-exact ascending-k chains per thread,
// write ping-pong global, R10-proven fence/atomic/spin barrier (tid0's
// gpu-scope fences CCTL.IVALL the SM's L1 -> no stale h).
// Dynamic smem: 32 KB (Us) + 64.5 KB (hs) + tok = ~96.6 KB.
// ---------------------------------------------------------------------------
#define P_SMEM_FLOATS (8192 + BBK * HS_STRIDE + 32)
#define P_SMEM_BYTES  (P_SMEM_FLOATS * 4)

__global__ void __launch_bounds__(256, 1)
rnn_persistent()
{
    extern __shared__ float sm[];
    float* Us = sm;                       // [128][16][4] = 8192 floats
    float* hs = sm + 8192;                // [32][516]
    int*   tok = (int*)(sm + 8192 + BBK * HS_STRIDE);

    const int tid = threadIdx.x;
    const int jsl = blockIdx.x & 31;      // j-slice 0..31
    const int bb  = blockIdx.x >> 5;      // b-block 0..3
    const int j0  = jsl * JW;
    const int b0  = bb * BBK;

    const int jl = tid & 15;
    const int bp = tid >> 4;              // b-pair 0..15
    const int bl0 = 2 * bp, bl1 = 2 * bp + 1;
    const int j  = j0 + jl;

    // ---- load U j-slice into smem once: Us[kq][jl][4] = U[4kq+i][j0+jl] ----
    const float* U = g_R.U;
    for (int idx = tid; idx < HID * JW; idx += 256) {
        int k = idx >> 4, jj = idx & 15;
        Us[(k >> 2) * 64 + jj * 4 + (k & 3)] = U[(size_t)k * HID + j0 + jj];
    }

    const float bh   = g_R.b_h[j];
    const int   is64 = g_R.is64;
    const long long* in64 = (const long long*)g_R.inputs;
    const int*       in32 = (const int*)g_R.inputs;

    volatile int* vbar = &g_bar;

    for (int t = 0; t < SEQ; ++t) {
        if (tid < BBK) {
            long long p = (long long)(b0 + tid) * SEQ + t;
            int v = is64 ? (int)in64[p] : in32[p];
            tok[tid] = min(max(v, 0), VOCAB - 1);
        }
        if (t > 0) {
            // contiguous 64 KB: g_H[t&1][b0*HID .. (b0+32)*HID)
            const float4* src = (const float4*)&g_H[t & 1][b0 * HID];
#pragma unroll
            for (int i = tid; i < (BBK * HID) / 4; i += 256) {
                int brow = i >> 7;          // 128 float4 per b row
                int k4   = i & 127;
                *(float4*)&hs[brow * HS_STRIDE + k4 * 4] = src[i];
            }
        }
        __syncthreads();

        // input-projection gathers (independent of the k-loop; issued early)
        float s10 = g_WE[(size_t)tok[bl0] * HID + j];
        float s11 = g_WE[(size_t)tok[bl1] * HID + j];

        float a0 = 0.f, a1 = 0.f;
        if (t > 0) {
            const float* up  = Us + jl * 4;
            const float* h0p = hs + bl0 * HS_STRIDE;
            const float* h1p = hs + bl1 * HS_STRIDE;
#pragma unroll 8
            for (int kq = 0; kq < 128; ++kq) {
                float4 u4  = *(const float4*)(up  + kq * 64);
                float4 h04 = *(const float4*)(h0p + kq * 4);
                float4 h14 = *(const float4*)(h1p + kq * 4);
                a0 = fmaf(h04.x, u4.x, a0); a1 = fmaf(h14.x, u4.x, a1);
                a0 = fmaf(h04.y, u4.y, a0); a1 = fmaf(h14.y, u4.y, a1);
                a0 = fmaf(h04.z, u4.z, a0); a1 = fmaf(h14.z, u4.z, a1);
                a0 = fmaf(h04.w, u4.w, a0); a1 = fmaf(h14.w, u4.w, a1);
            }
        }

        float* Hd = g_H[(t + 1) & 1];
        Hd[(b0 + bl0) * HID + j] = xla_tanh((s10 + a0) + bh);
        Hd[(b0 + bl1) * HID + j] = xla_tanh((s11 + a1) + bh);

        if (t + 1 < SEQ) {
            // R10-proven inter-CTA barrier (release/acquire via tid0 fences)
            __syncthreads();
            if (tid == 0) {
                __threadfence();
                atomicAdd(&g_bar, 1);
                int target = NCTA * (t + 1);
                while (*vbar < target) { }
                __threadfence();
            }
            __syncthreads();
        }
    }
}

// ---------------------------------------------------------------------------
// FALLBACK per-step kernel (R16, proven): used only if the dynamic-smem
// attribute opt-in fails on this stack.
// ---------------------------------------------------------------------------
__global__ void __launch_bounds__(128)
rnn_step_fast(int t)
{
    __shared__ float4 hsT[HID];
    __shared__ int    tok4[4];

    const int tid = threadIdx.x;
    const int jb  = blockIdx.x & 3;
    const int bg  = blockIdx.x >> 2;
    const int b0  = bg * 4;
    const int j   = jb * 128 + tid;

    if (tid < 4) {
        long long p = (long long)(b0 + tid) * SEQ + t;
        int v = g_R.is64 ? (int)((const long long*)g_R.inputs)[p]
                         : ((const int*)g_R.inputs)[p];
        tok4[tid] = min(max(v, 0), VOCAB - 1);
    }
    if (t > 0) {
        const float* Hs = &g_H[t & 1][0];
#pragma unroll
        for (int q = 0; q < 4; ++q) {
            int k = tid * 4 + q;
            hsT[k] = make_float4(Hs[(b0 + 0) * HID + k], Hs[(b0 + 1) * HID + k],
                                 Hs[(b0 + 2) * HID + k], Hs[(b0 + 3) * HID + k]);
        }
    }
    __syncthreads();

    const float* WE = g_WE;
    float s10 = WE[(size_t)tok4[0] * HID + j];
    float s11 = WE[(size_t)tok4[1] * HID + j];
    float s12 = WE[(size_t)tok4[2] * HID + j];
    float s13 = WE[(size_t)tok4[3] * HID + j];
    float bh  = g_R.b_h[j];

    float a0 = 0.f, a1 = 0.f, a2 = 0.f, a3 = 0.f;
    if (t > 0) {
        const float* Uj = g_R.U + j;
        float ub[32];
#pragma unroll
        for (int s = 0; s < 32; ++s) ub[s] = Uj[(size_t)s * HID];
#pragma unroll 32
        for (int k = 0; k < HID; ++k) {
            float u = ub[k & 31];
            ub[k & 31] = Uj[(size_t)((k + 32) & (HID - 1)) * HID];
            float4 hv = hsT[k];
            a0 = fmaf(hv.x, u, a0);
            a1 = fmaf(hv.y, u, a1);
            a2 = fmaf(hv.z, u, a2);
            a3 = fmaf(hv.w, u, a3);
        }
    }

    float* Hd = g_H[(t + 1) & 1];
    Hd[(b0 + 0) * HID + j] = xla_tanh((s10 + a0) + bh);
    Hd[(b0 + 1) * HID + j] = xla_tanh((s11 + a1) + bh);
    Hd[(b0 + 2) * HID + j] = xla_tanh((s12 + a2) + bh);
    Hd[(b0 + 3) * HID + j] = xla_tanh((s13 + a3) + bh);
}

// ---------------------------------------------------------------------------
// Head: logits = h_T @ V + b_q, softmax. h_T in g_H[0], layout [b][k].
// ---------------------------------------------------------------------------
__global__ void head_kernel(float* __restrict__ out)
{
    const float* V   = g_R.V;
    const float* b_q = g_R.b_q;

    const int b    = blockIdx.x;
    const int lane = threadIdx.x;
    const float* h = &g_H[0][b * HID];

    float acc[NOUT];
#pragma unroll
    for (int n = 0; n < NOUT; ++n) acc[n] = 0.f;

    for (int k = lane; k < HID; k += 32) {
        float hv = h[k];
        const float* vr = &V[k * NOUT];
#pragma unroll
        for (int n = 0; n < NOUT; ++n) acc[n] = fmaf(hv, vr[n], acc[n]);
    }
#pragma unroll
    for (int off = 16; off > 0; off >>= 1) {
#pragma unroll
        for (int n = 0; n < NOUT; ++n)
            acc[n] += __shfl_down_sync(0xffffffffu, acc[n], off);
    }
    if (lane == 0) {
        float logits[NOUT], mx = -1e30f;
#pragma unroll
        for (int n = 0; n < NOUT; ++n) { logits[n] = acc[n] + b_q[n]; mx = fmaxf(mx, logits[n]); }
        float se = 0.f;
#pragma unroll
        for (int n = 0; n < NOUT; ++n) { logits[n] = expf(logits[n] - mx); se += logits[n]; }
        float inv = __fdiv_rn(1.0f, se);
#pragma unroll
        for (int n = 0; n < NOUT; ++n) out[b * NOUT + n] = logits[n] * inv;
    }
}

// ---------------------------------------------------------------------------
// Launch: resolver (+barrier reset), WE GEMM, persistent recurrence (with
// deterministic fallback to per-step launches if the smem opt-in fails), head.
// ---------------------------------------------------------------------------
extern "C" void kernel_launch(void* const* d_in, const int* in_sizes, int n_in,
                              void* d_out, int out_size)
{
    RawIn r;
    r.n = (n_in < 7) ? n_in : 7;
    for (int i = 0; i < 7; ++i) {
        int ii = (i < n_in) ? i : (n_in - 1);
        r.p[i]  = d_in[ii];
        r.sz[i] = (long long)in_sizes[ii];
    }

    // Opt-in for ~96.6 KB dynamic smem; stable result => deterministic branch.
    cudaError_t attr_ok = cudaFuncSetAttribute(
        rnn_persistent, cudaFuncAttributeMaxDynamicSharedMemorySize, P_SMEM_BYTES);

    resolve_kernel<<<1, 1>>>(r);

    dim3 grid1((VOCAB + 63) / 64, HID / 64);   // 782 x 8
    we_gemm_kernel<<<grid1, 256>>>();

    if (attr_ok == cudaSuccess) {
        rnn_persistent<<<NCTA, 256, P_SMEM_BYTES>>>();
    } else {
        for (int t = 0; t < SEQ; ++t)
            rnn_step_fast<<<BATCH, 128>>>(t);
    }

    head_kernel<<<BATCH, 32>>>((float*)d_out);
}